// round 16
// baseline (speedup 1.0000x reference)
#include <cuda_runtime.h>
#include <cuda_bf16.h>
#include <cstdint>

#define Bq 4
#define Vq 50000
#define Cq 160
#define V_CTA 128         // vertices per CTA (4 warps x m32)
#define NTHR 128
#define KP 10             // kstep-pairs: 160 / 16 (each pair = 2 x k8 mma)
#define NT 6              // 48 / 8
#define SB_U32 (KP * NT * 32 * 4)     // 7680 u32 = 30720B (B tf32 frags)
#define SMEM_BYTES (SB_U32 * 4)       // D scratch (128*49*4=25088B) aliases

// ---------------- helpers ----------------
__device__ __forceinline__ uint32_t f2tf32(float f) {
    uint32_t r;
    asm("cvt.rna.tf32.f32 %0, %1;" : "=r"(r) : "f"(f));
    return r;
}
__device__ __forceinline__ void mma1688(float* d,
                                        uint32_t a0, uint32_t a1,
                                        uint32_t a2, uint32_t a3,
                                        uint32_t b0, uint32_t b1) {
    asm("mma.sync.aligned.m16n8k8.row.col.f32.tf32.tf32.f32 "
        "{%0,%1,%2,%3}, {%4,%5,%6,%7}, {%8,%9}, {%0,%1,%2,%3};"
        : "+f"(d[0]), "+f"(d[1]), "+f"(d[2]), "+f"(d[3])
        : "r"(a0), "r"(a1), "r"(a2), "r"(a3), "r"(b0), "r"(b1));
}

// ---------------- Single fused kernel ----------------
// Phase 0: all 640 (b,c) G-entries recomputed per CTA, written as permuted
//          tf32 .col fragments directly into smem (no precompute kernel,
//          no gmem B table, no B copy).
// Phase 1: m32-per-warp tf32 GEMM with register-double-buffered B LDS.
// Phase 2: D shuffle through smem (aliases B) + affine epilogue.
__global__ void __launch_bounds__(NTHR, 3)
main_kernel(const float* __restrict__ W,
            const float* __restrict__ X,
            const float* __restrict__ Vn,
            const float* __restrict__ r6,
            const int* __restrict__ idx,
            float* __restrict__ out) {
    extern __shared__ __align__(16) unsigned int smem[];
    unsigned int* sB = smem;

    int tid = threadIdx.x, wid = tid >> 5, lane = tid & 31;
    int g = lane >> 2, t = lane & 3;
    int vbase = blockIdx.x * V_CTA;

    // --- W pointers + kstep-pair 0 prefetch (fire LDGs before G math) ---
    const float* wp[4];
    #pragma unroll
    for (int i = 0; i < 4; i++) {
        int r = min(vbase + wid * 32 + g + 8 * i, Vq - 1);
        wp[i] = W + (size_t)r * Cq + 4 * t;
    }
    float4 cur0 = *(const float4*)wp[0];
    float4 cur1 = *(const float4*)wp[1];
    float4 cur2 = *(const float4*)wp[2];
    float4 cur3 = *(const float4*)wp[3];

    // --- Phase 0: build B fragments in smem (5 items per thread) ---
    for (int i = tid; i < Bq * Cq; i += NTHR) {
        int b = i / Cq, c = i % Cq;

        const float* d6 = r6 + (size_t)(b * Cq + c) * 6;
        float a1x = d6[0], a1y = d6[1], a1z = d6[2];
        float a2x = d6[3], a2y = d6[4], a2z = d6[5];

        float n1 = fmaxf(sqrtf(a1x*a1x + a1y*a1y + a1z*a1z), 1e-8f);
        float b1x = a1x/n1, b1y = a1y/n1, b1z = a1z/n1;
        float dt = b1x*a2x + b1y*a2y + b1z*a2z;
        float px = a2x - dt*b1x, py = a2y - dt*b1y, pz = a2z - dt*b1z;
        float n2 = fmaxf(sqrtf(px*px + py*py + pz*pz), 1e-8f);
        float b2x = px/n2, b2y = py/n2, b2z = pz/n2;
        float b3x = b1y*b2z - b1z*b2y;
        float b3y = b1z*b2x - b1x*b2z;
        float b3z = b1x*b2y - b1y*b2x;

        float R[3][3] = {{b1x,b1y,b1z},{b2x,b2y,b2z},{b3x,b3y,b3z}};

        int vi = idx[c];
        vi = max(0, min(Vq - 1, vi));
        const float* xc = X + ((size_t)b * Vq + vi) * 3;
        float cen0 = xc[0], cen1 = xc[1], cen2 = xc[2];
        const float* vn = Vn + (size_t)(b * Cq + c) * 3;

        float gg[12];
        #pragma unroll
        for (int k = 0; k < 3; k++) {
            #pragma unroll
            for (int d = 0; d < 3; d++) gg[k*3 + d] = R[k][d];
            gg[9 + k] = ((k == 0) ? cen0 : (k == 1) ? cen1 : cen2) + vn[k]
                      - (R[k][0]*cen0 + R[k][1]*cen1 + R[k][2]*cen2);
        }

        // actual k = c: p = c>>4; within pair t = (c&15)>>2, j = c&3
        int p  = c >> 4, klo = c & 15;
        int tq = klo >> 2;
        int j  = klo & 3;
        #pragma unroll
        for (int jj = 0; jj < 12; jj++) {
            int n = jj * 4 + b;
            int ln = (n & 7) * 4 + tq;
            int slot = ((p * NT + (n >> 3)) * 32 + ln) * 4 + j;
            sB[slot] = f2tf32(gg[jj]);
        }
    }
    __syncthreads();

    // --- Phase 1: GEMM mainloop ---
    float d0[NT][4], d1[NT][4];
    #pragma unroll
    for (int nt = 0; nt < NT; nt++)
        #pragma unroll
        for (int r = 0; r < 4; r++) { d0[nt][r] = 0.0f; d1[nt][r] = 0.0f; }

    // B double-buffer: load pair 0 fragments
    uint4 bb[NT];
    #pragma unroll
    for (int nt = 0; nt < NT; nt++)
        bb[nt] = *(const uint4*)&sB[((0 * NT + nt) * 32 + lane) * 4];

    #pragma unroll
    for (int p = 0; p < KP; p++) {
        // prefetch next W chunk
        float4 n0, n1, n2, n3;
        if (p + 1 < KP) {
            n0 = *(const float4*)(wp[0] + (p + 1) * 16);
            n1 = *(const float4*)(wp[1] + (p + 1) * 16);
            n2 = *(const float4*)(wp[2] + (p + 1) * 16);
            n3 = *(const float4*)(wp[3] + (p + 1) * 16);
        }
        // prefetch next B fragments (LDS issued before the MMA block)
        uint4 nbb[NT];
        if (p + 1 < KP) {
            #pragma unroll
            for (int nt = 0; nt < NT; nt++)
                nbb[nt] = *(const uint4*)&sB[(((p + 1) * NT + nt) * 32 + lane) * 4];
        }

        uint32_t t0x = f2tf32(cur0.x), t0y = f2tf32(cur0.y),
                 t0z = f2tf32(cur0.z), t0w = f2tf32(cur0.w);
        uint32_t t1x = f2tf32(cur1.x), t1y = f2tf32(cur1.y),
                 t1z = f2tf32(cur1.z), t1w = f2tf32(cur1.w);
        uint32_t t2x = f2tf32(cur2.x), t2y = f2tf32(cur2.y),
                 t2z = f2tf32(cur2.z), t2w = f2tf32(cur2.w);
        uint32_t t3x = f2tf32(cur3.x), t3y = f2tf32(cur3.y),
                 t3z = f2tf32(cur3.z), t3w = f2tf32(cur3.w);

        #pragma unroll
        for (int nt = 0; nt < NT; nt++) {
            mma1688(d0[nt], t0x, t1x, t0y, t1y, bb[nt].x, bb[nt].y);
            mma1688(d1[nt], t2x, t3x, t2y, t3y, bb[nt].x, bb[nt].y);
            mma1688(d0[nt], t0z, t1z, t0w, t1w, bb[nt].z, bb[nt].w);
            mma1688(d1[nt], t2z, t3z, t2w, t3w, bb[nt].z, bb[nt].w);
        }

        #pragma unroll
        for (int nt = 0; nt < NT; nt++) bb[nt] = nbb[nt];
        cur0 = n0; cur1 = n1; cur2 = n2; cur3 = n3;
    }

    // --- Phase 2: epilogue ---
    // hoist the X gather so its latency hides behind the D shuffle
    int v = vbase + tid;
    float xv[12];
    if (v < Vq) {
        #pragma unroll
        for (int b = 0; b < Bq; b++) {
            const float* xp = X + ((size_t)b * Vq + v) * 3;
            xv[b*3]   = xp[0];
            xv[b*3+1] = xp[1];
            xv[b*3+2] = xp[2];
        }
    }

    __syncthreads();   // B dead; alias as D scratch [128][49]
    float* Dsm = (float*)sB;
    #pragma unroll
    for (int nt = 0; nt < NT; nt++) {
        int col = nt * 8 + 2 * t;
        int q0 = (wid * 32 + g) * 49;
        int q1 = (wid * 32 + g + 8) * 49;
        int q2 = (wid * 32 + g + 16) * 49;
        int q3 = (wid * 32 + g + 24) * 49;
        Dsm[q0 + col] = d0[nt][0]; Dsm[q0 + col + 1] = d0[nt][1];
        Dsm[q1 + col] = d0[nt][2]; Dsm[q1 + col + 1] = d0[nt][3];
        Dsm[q2 + col] = d1[nt][0]; Dsm[q2 + col + 1] = d1[nt][1];
        Dsm[q3 + col] = d1[nt][2]; Dsm[q3 + col + 1] = d1[nt][3];
    }
    __syncthreads();

    if (v < Vq) {
        #pragma unroll
        for (int b = 0; b < Bq; b++) {
            float m[12];
            #pragma unroll
            for (int j = 0; j < 12; j++) m[j] = Dsm[tid * 49 + j * 4 + b];
            float x0 = xv[b*3], x1 = xv[b*3+1], x2 = xv[b*3+2];
            float* op = out + ((size_t)b * Vq + v) * 3;
            op[0] = m[9]  + m[0]*x0 + m[1]*x1 + m[2]*x2;
            op[1] = m[10] + m[3]*x0 + m[4]*x1 + m[5]*x2;
            op[2] = m[11] + m[6]*x0 + m[7]*x1 + m[8]*x2;
        }
    }
}

// ---------------- launch ----------------
extern "C" void kernel_launch(void* const* d_in, const int* in_sizes, int n_in,
                              void* d_out, int out_size) {
    const float* X   = (const float*)d_in[0];
    const float* Vn  = (const float*)d_in[1];
    const float* r6  = (const float*)d_in[2];
    const float* W   = (const float*)d_in[3];
    const int*   idx = (const int*)d_in[4];   // JAX x64-disabled: int64 -> int32
    float* out = (float*)d_out;

    cudaFuncSetAttribute(main_kernel,
                         cudaFuncAttributeMaxDynamicSharedMemorySize, SMEM_BYTES);
    int grid = (Vq + V_CTA - 1) / V_CTA;    // 391
    main_kernel<<<grid, NTHR, SMEM_BYTES>>>(W, X, Vn, r6, idx, out);
}

// round 17
// speedup vs baseline: 1.0171x; 1.0171x over previous
#include <cuda_runtime.h>
#include <cuda_bf16.h>
#include <cstdint>

#define Bq 4
#define Vq 50000
#define Cq 160
#define V_CTA 128         // vertices per CTA (4 m32 tiles)
#define NTHR 256          // 8 warps: 4 m-tiles x 2 K-halves
#define KP 10             // kstep-pairs total (160/16)
#define KH 5              // kstep-pairs per K-half
#define NT 6              // 48 / 8
#define SB_U32 (KP * NT * 32 * 4)     // 7680 u32 = 30720B (B tf32 frags)
#define SMEM_BYTES (SB_U32 * 4)       // D scratch (128*49*4=25088B) aliases

// B operand (G) in gmem as tf32 words:
// u32 [p][nt][lane][j], j=0..3: (mma0.b0, mma0.b1, mma1.b0, mma1.b1)
// k-mapping: thread t owns actual k = p*16 + 4t + j.
__device__ __align__(16) unsigned int g_bfrag[SB_U32];

// ---------------- Precompute: G -> permuted tf32 .col B fragments -----------
__global__ void precompute_kernel(const float* __restrict__ X,
                                  const float* __restrict__ Vn,
                                  const float* __restrict__ r6,
                                  const int* __restrict__ idx) {
    int i = blockIdx.x * blockDim.x + threadIdx.x;
    if (i >= Bq * Cq) return;
    int b = i / Cq, c = i % Cq;

    const float* d6 = r6 + (size_t)(b * Cq + c) * 6;
    float a1x = d6[0], a1y = d6[1], a1z = d6[2];
    float a2x = d6[3], a2y = d6[4], a2z = d6[5];

    float n1 = fmaxf(sqrtf(a1x*a1x + a1y*a1y + a1z*a1z), 1e-8f);
    float b1x = a1x/n1, b1y = a1y/n1, b1z = a1z/n1;
    float dt = b1x*a2x + b1y*a2y + b1z*a2z;
    float px = a2x - dt*b1x, py = a2y - dt*b1y, pz = a2z - dt*b1z;
    float n2 = fmaxf(sqrtf(px*px + py*py + pz*pz), 1e-8f);
    float b2x = px/n2, b2y = py/n2, b2z = pz/n2;
    float b3x = b1y*b2z - b1z*b2y;
    float b3y = b1z*b2x - b1x*b2z;
    float b3z = b1x*b2y - b1y*b2x;

    float R[3][3] = {{b1x,b1y,b1z},{b2x,b2y,b2z},{b3x,b3y,b3z}};

    int vi = idx[c];
    vi = max(0, min(Vq - 1, vi));
    const float* xc = X + ((size_t)b * Vq + vi) * 3;
    float cen[3] = {xc[0], xc[1], xc[2]};
    const float* vn = Vn + (size_t)(b * Cq + c) * 3;

    float g[12];
    #pragma unroll
    for (int k = 0; k < 3; k++) {
        #pragma unroll
        for (int d = 0; d < 3; d++) g[k*3 + d] = R[k][d];
        g[9 + k] = cen[k] + vn[k]
                 - (R[k][0]*cen[0] + R[k][1]*cen[1] + R[k][2]*cen[2]);
    }

    int p   = c >> 4, klo = c & 15;
    int t   = klo >> 2;
    int j   = klo & 3;

    #pragma unroll
    for (int jj = 0; jj < 12; jj++) {
        int n = jj * 4 + b;
        int lane = (n & 7) * 4 + t;
        int slot = ((p * NT + (n >> 3)) * 32 + lane) * 4 + j;
        uint32_t tv;
        asm("cvt.rna.tf32.f32 %0, %1;" : "=r"(tv) : "f"(g[jj]));
        g_bfrag[slot] = tv;
    }
}

// ---------------- helpers ----------------
__device__ __forceinline__ uint32_t f2tf32(float f) {
    uint32_t r;
    asm("cvt.rna.tf32.f32 %0, %1;" : "=r"(r) : "f"(f));
    return r;
}
__device__ __forceinline__ void mma1688(float* d,
                                        uint32_t a0, uint32_t a1,
                                        uint32_t a2, uint32_t a3,
                                        uint32_t b0, uint32_t b1) {
    asm("mma.sync.aligned.m16n8k8.row.col.f32.tf32.tf32.f32 "
        "{%0,%1,%2,%3}, {%4,%5,%6,%7}, {%8,%9}, {%0,%1,%2,%3};"
        : "+f"(d[0]), "+f"(d[1]), "+f"(d[2]), "+f"(d[3])
        : "r"(a0), "r"(a1), "r"(a2), "r"(a3), "r"(b0), "r"(b1));
}

// ------- Main kernel: 8 warps = 4 m32-tiles x 2 K-halves ----------
__global__ void __launch_bounds__(NTHR, 2)
main_kernel(const float* __restrict__ W,
            const float* __restrict__ X,
            float* __restrict__ out) {
    extern __shared__ __align__(16) unsigned int smem[];
    unsigned int* sB = smem;

    int tid = threadIdx.x, wid = tid >> 5, lane = tid & 31;
    int g = lane >> 2, t = lane & 3;
    int mt = wid & 3;            // m32 tile
    int kh = wid >> 2;           // K-half (kpairs kh*5 .. kh*5+4)
    int vbase = blockIdx.x * V_CTA;

    // 4 fragment row-groups per warp within tile mt
    const float* wp[4];
    #pragma unroll
    for (int i = 0; i < 4; i++) {
        int r = min(vbase + mt * 32 + g + 8 * i, Vq - 1);
        wp[i] = W + (size_t)r * Cq + kh * (KH * 16) + 4 * t;
    }

    // Prefetch first kpair of this K-half
    float4 cur0 = *(const float4*)wp[0];
    float4 cur1 = *(const float4*)wp[1];
    float4 cur2 = *(const float4*)wp[2];
    float4 cur3 = *(const float4*)wp[3];

    // Copy B fragments to smem (30720B)
    {
        const uint4* src = (const uint4*)g_bfrag;
        uint4* dst = (uint4*)sB;
        #pragma unroll
        for (int i = tid; i < SB_U32 / 4; i += NTHR) dst[i] = src[i];
    }
    __syncthreads();

    float d0[NT][4], d1[NT][4];
    #pragma unroll
    for (int nt = 0; nt < NT; nt++)
        #pragma unroll
        for (int r = 0; r < 4; r++) { d0[nt][r] = 0.0f; d1[nt][r] = 0.0f; }

    // B double-buffer: load first pair of this K-half
    uint4 bb[NT];
    #pragma unroll
    for (int nt = 0; nt < NT; nt++)
        bb[nt] = *(const uint4*)&sB[(((kh * KH) * NT + nt) * 32 + lane) * 4];

    #pragma unroll
    for (int i = 0; i < KH; i++) {
        int p = kh * KH + i;
        float4 n0, n1, n2, n3;
        uint4 nbb[NT];
        if (i + 1 < KH) {
            n0 = *(const float4*)(wp[0] + (i + 1) * 16);
            n1 = *(const float4*)(wp[1] + (i + 1) * 16);
            n2 = *(const float4*)(wp[2] + (i + 1) * 16);
            n3 = *(const float4*)(wp[3] + (i + 1) * 16);
            #pragma unroll
            for (int nt = 0; nt < NT; nt++)
                nbb[nt] = *(const uint4*)&sB[(((p + 1) * NT + nt) * 32 + lane) * 4];
        }

        uint32_t t0x = f2tf32(cur0.x), t0y = f2tf32(cur0.y),
                 t0z = f2tf32(cur0.z), t0w = f2tf32(cur0.w);
        uint32_t t1x = f2tf32(cur1.x), t1y = f2tf32(cur1.y),
                 t1z = f2tf32(cur1.z), t1w = f2tf32(cur1.w);
        uint32_t t2x = f2tf32(cur2.x), t2y = f2tf32(cur2.y),
                 t2z = f2tf32(cur2.z), t2w = f2tf32(cur2.w);
        uint32_t t3x = f2tf32(cur3.x), t3y = f2tf32(cur3.y),
                 t3z = f2tf32(cur3.z), t3w = f2tf32(cur3.w);

        #pragma unroll
        for (int nt = 0; nt < NT; nt++) {
            mma1688(d0[nt], t0x, t1x, t0y, t1y, bb[nt].x, bb[nt].y);
            mma1688(d1[nt], t2x, t3x, t2y, t3y, bb[nt].x, bb[nt].y);
            mma1688(d0[nt], t0z, t1z, t0w, t1w, bb[nt].z, bb[nt].w);
            mma1688(d1[nt], t2z, t3z, t2w, t3w, bb[nt].z, bb[nt].w);
        }

        #pragma unroll
        for (int nt = 0; nt < NT; nt++) bb[nt] = nbb[nt];
        cur0 = n0; cur1 = n1; cur2 = n2; cur3 = n3;
    }

    // hoist epilogue X gather (latency hides behind the D combine)
    int vl = tid >> 1;                 // vertex within CTA
    int bsel = tid & 1;                // batches 2*bsel, 2*bsel+1
    int v = vbase + vl;
    float xv[6];
    if (v < Vq) {
        #pragma unroll
        for (int b2 = 0; b2 < 2; b2++) {
            int b = 2 * bsel + b2;
            const float* xp = X + ((size_t)b * Vq + v) * 3;
            xv[b2*3]   = xp[0];
            xv[b2*3+1] = xp[1];
            xv[b2*3+2] = xp[2];
        }
    }

    // ---- combine K-halves in D scratch [128][49] (aliases sB) ----
    __syncthreads();                   // ALL warps done reading sB
    float* Dsm = (float*)sB;
    if (kh == 0) {
        #pragma unroll
        for (int nt = 0; nt < NT; nt++) {
            int col = nt * 8 + 2 * t;
            int q0 = (mt * 32 + g) * 49;
            int q1 = (mt * 32 + g + 8) * 49;
            int q2 = (mt * 32 + g + 16) * 49;
            int q3 = (mt * 32 + g + 24) * 49;
            Dsm[q0 + col] = d0[nt][0]; Dsm[q0 + col + 1] = d0[nt][1];
            Dsm[q1 + col] = d0[nt][2]; Dsm[q1 + col + 1] = d0[nt][3];
            Dsm[q2 + col] = d1[nt][0]; Dsm[q2 + col + 1] = d1[nt][1];
            Dsm[q3 + col] = d1[nt][2]; Dsm[q3 + col + 1] = d1[nt][3];
        }
    }
    __syncthreads();
    if (kh == 1) {
        #pragma unroll
        for (int nt = 0; nt < NT; nt++) {
            int col = nt * 8 + 2 * t;
            int q0 = (mt * 32 + g) * 49;
            int q1 = (mt * 32 + g + 8) * 49;
            int q2 = (mt * 32 + g + 16) * 49;
            int q3 = (mt * 32 + g + 24) * 49;
            Dsm[q0 + col]     += d0[nt][0];
            Dsm[q0 + col + 1] += d0[nt][1];
            Dsm[q1 + col]     += d0[nt][2];
            Dsm[q1 + col + 1] += d0[nt][3];
            Dsm[q2 + col]     += d1[nt][0];
            Dsm[q2 + col + 1] += d1[nt][1];
            Dsm[q3 + col]     += d1[nt][2];
            Dsm[q3 + col + 1] += d1[nt][3];
        }
    }
    __syncthreads();

    // Epilogue: thread = (vertex, batch-pair); 256 = 128 x 2
    if (v < Vq) {
        #pragma unroll
        for (int b2 = 0; b2 < 2; b2++) {
            int b = 2 * bsel + b2;
            float m[12];
            #pragma unroll
            for (int j = 0; j < 12; j++) m[j] = Dsm[vl * 49 + j * 4 + b];
            float x0 = xv[b2*3], x1 = xv[b2*3+1], x2 = xv[b2*3+2];
            float* op = out + ((size_t)b * Vq + v) * 3;
            op[0] = m[9]  + m[0]*x0 + m[1]*x1 + m[2]*x2;
            op[1] = m[10] + m[3]*x0 + m[4]*x1 + m[5]*x2;
            op[2] = m[11] + m[6]*x0 + m[7]*x1 + m[8]*x2;
        }
    }
}

// ---------------- launch ----------------
extern "C" void kernel_launch(void* const* d_in, const int* in_sizes, int n_in,
                              void* d_out, int out_size) {
    const float* X   = (const float*)d_in[0];
    const float* Vn  = (const float*)d_in[1];
    const float* r6  = (const float*)d_in[2];
    const float* W   = (const float*)d_in[3];
    const int*   idx = (const int*)d_in[4];   // JAX x64-disabled: int64 -> int32
    float* out = (float*)d_out;

    precompute_kernel<<<(Bq * Cq + 127) / 128, 128>>>(X, Vn, r6, idx);

    cudaFuncSetAttribute(main_kernel,
                         cudaFuncAttributeMaxDynamicSharedMemorySize, SMEM_BYTES);
    int grid = (Vq + V_CTA - 1) / V_CTA;    // 391
    main_kernel<<<grid, NTHR, SMEM_BYTES>>>(W, X, out);
}